// round 16
// baseline (speedup 1.0000x reference)
#include <cuda_runtime.h>
#include <cuda_bf16.h>
#include <cstdint>

// out[t, :] = W[x[t], :] + b    t in [0, 8192), D = 2048
//
// Depth-3 cp.async (LDGSTS) pipeline: row data lands in SMEM instead of
// registers, so pipeline depth costs no occupancy (the register file capped
// all register-pipelined variants at depth 1 / 32 regs). 6 outstanding 16B
// copies per thread at full 8 CTA/SM occupancy = ~3x the in-flight bytes of
// the register version. Each thread consumes exactly the smem it copied, so
// cp.async.wait_group is the only synchronization needed — zero barriers.

#define D_MODEL 2048
#define D4      (D_MODEL / 4)   // 512 float4 per row
#define TOKENS  8192
#define GRID    1184            // 8 CTAs/SM * 148 SMs, exactly resident
#define NTHR    256
#define NBUF    3

__device__ __forceinline__ uint32_t smem_u32(const void* p) {
    uint32_t a;
    asm("{ .reg .u64 t; cvta.to.shared.u64 t, %1; cvt.u32.u64 %0, t; }"
        : "=r"(a) : "l"(p));
    return a;
}

__device__ __forceinline__ void cpa16(uint32_t sdst, const void* gsrc) {
    asm volatile("cp.async.cg.shared.global [%0], [%1], 16;"
                 :: "r"(sdst), "l"(gsrc) : "memory");
}

__device__ __forceinline__ void cpa_commit() {
    asm volatile("cp.async.commit_group;" ::: "memory");
}

__global__ __launch_bounds__(NTHR, 8)
void embed_gather_cpasync(const int* __restrict__ x,
                          const float4* __restrict__ W4,
                          const float4* __restrict__ b4,
                          float4* __restrict__ out4) {
    __shared__ alignas(16) float4 buf[NBUF][D4];   // 24 KB ring

    const int tid = threadIdx.x;
    const int bid = blockIdx.x;
    const int c0 = tid;
    const int c1 = tid + NTHR;

    const float4 bb0 = b4[c0];
    const float4 bb1 = b4[c1];

    // this thread's two smem slots in each buffer
    uint32_t s0[NBUF], s1[NBUF];
#pragma unroll
    for (int k = 0; k < NBUF; k++) {
        s0[k] = smem_u32(&buf[k][c0]);
        s1[k] = smem_u32(&buf[k][c1]);
    }

    // prologue: fill the ring (bid + 2*GRID <= 2367+2368 = 4735 < 8192, all valid)
#pragma unroll
    for (int k = 0; k < NBUF; k++) {
        const int t = bid + k * GRID;
        const unsigned o = (unsigned)__ldg(x + t) * D4;
        cpa16(s0[k], W4 + o + c0);
        cpa16(s1[k], W4 + o + c1);
        cpa_commit();
    }

    int i = 0;
    for (int t = bid; t < TOKENS; t += GRID, ++i) {
        const int p = i % NBUF;

        // group i complete when <= NBUF-1 groups remain pending
        asm volatile("cp.async.wait_group %0;" :: "n"(NBUF - 1) : "memory");

        float4 v0 = buf[p][c0];     // own thread's data: no barrier needed
        float4 v1 = buf[p][c1];
        v0.x += bb0.x; v0.y += bb0.y; v0.z += bb0.z; v0.w += bb0.w;
        v1.x += bb1.x; v1.y += bb1.y; v1.z += bb1.z; v1.w += bb1.w;

        float4* __restrict__ dst = out4 + (unsigned)t * D4;
        __stcs(dst + c0, v0);
        __stcs(dst + c1, v1);

        // refill this slot with the token NBUF iterations ahead
        const int tn = t + NBUF * GRID;
        if (tn < TOKENS) {
            const unsigned o = (unsigned)__ldg(x + tn) * D4;
            cpa16(s0[p], W4 + o + c0);
            cpa16(s1[p], W4 + o + c1);
        }
        cpa_commit();   // commit every iteration (possibly empty) to keep group count uniform
    }
}

extern "C" void kernel_launch(void* const* d_in, const int* in_sizes, int n_in,
                              void* d_out, int out_size) {
    const int*    x = (const int*)d_in[0];        // [4, 2048] int32
    const float4* W = (const float4*)d_in[1];     // [50257, 2048] f32
    const float4* b = (const float4*)d_in[2];     // [2048] f32
    float4* out = (float4*)d_out;                 // [4, 2048, 2048] f32

    embed_gather_cpasync<<<GRID, NTHR>>>(x, W, b, out);
}

// round 17
// speedup vs baseline: 1.0293x; 1.0293x over previous
#include <cuda_runtime.h>
#include <cuda_bf16.h>

// out[t, :] = W[x[t], :] + b    t in [0, 8192), D = 2048
//
// FINAL (champion, best measured 18.53us; re-verified 18.78us).
// Persistent depth-1 software-pipelined gather. Empirical roof for this
// pattern is ~18.5-19us: 128 MB compulsory traffic (64 MB random 8KB row
// reads + 64 MB output writes) with exposed gather latency. Measured-neutral
// or worse alternatives: TMA bulk loads (22.8us) / bulk stores (29.4us),
// cp.async depth-3 smem ring (21.7us), register pipeline depth-2 (21.6us,
// occupancy loss), MLP 2->8 sweeps, all cache policies (.cs/.wt/.ldcs),
// index/ALU micro-trims. Config: GRID = 1184 = 8 CTAs/SM x 148 SMs (exactly
// resident), next token's row loads issue while the current token is
// consumed, indices prefetched two iterations ahead, evict-first stores.

#define D_MODEL 2048
#define D4      (D_MODEL / 4)   // 512 float4 per row
#define TOKENS  8192
#define GRID    1184            // 8 CTAs/SM * 148 SMs
#define NTHR    256

__global__ __launch_bounds__(NTHR, 8)
void embed_gather_pipe(const int* __restrict__ x,
                       const float4* __restrict__ W4,
                       const float4* __restrict__ b4,
                       float4* __restrict__ out4) {
    const int c0 = threadIdx.x;
    const int c1 = threadIdx.x + NTHR;

    const float4 bb0 = b4[c0];
    const float4 bb1 = b4[c1];

    int t = blockIdx.x;                      // GRID < TOKENS, always valid
    int t1 = t + GRID;

    // prologue: current row loads + next index
    long long r_cur = (long long)__ldg(x + t);
    long long r_nxt = (t1 < TOKENS) ? (long long)__ldg(x + t1) : 0;

    float4 a0 = W4[r_cur * D4 + c0];
    float4 a1 = W4[r_cur * D4 + c1];

    for (;;) {
        const bool have_next = (t1 < TOKENS);

        // prefetch index two ahead (hides idx->row dependency)
        const int t2 = t1 + GRID;
        const long long r_nxt2 = (t2 < TOKENS) ? (long long)__ldg(x + t2) : 0;

        // issue next row's loads BEFORE consuming current (independent of stores)
        float4 n0, n1;
        if (have_next) {
            n0 = W4[r_nxt * D4 + c0];
            n1 = W4[r_nxt * D4 + c1];
        }

        // consume current token
        float4 v0 = a0, v1 = a1;
        v0.x += bb0.x; v0.y += bb0.y; v0.z += bb0.z; v0.w += bb0.w;
        v1.x += bb1.x; v1.y += bb1.y; v1.z += bb1.z; v1.w += bb1.w;

        float4* __restrict__ dst = out4 + (long long)t * D4;
        __stcs(dst + c0, v0);
        __stcs(dst + c1, v1);

        if (!have_next) break;
        t = t1; t1 = t2;
        r_nxt = r_nxt2;
        a0 = n0; a1 = n1;
    }
}

extern "C" void kernel_launch(void* const* d_in, const int* in_sizes, int n_in,
                              void* d_out, int out_size) {
    const int*    x = (const int*)d_in[0];        // [4, 2048] int32
    const float4* W = (const float4*)d_in[1];     // [50257, 2048] f32
    const float4* b = (const float4*)d_in[2];     // [2048] f32
    float4* out = (float4*)d_out;                 // [4, 2048, 2048] f32

    embed_gather_pipe<<<GRID, NTHR>>>(x, W, b, out);
}